// round 12
// baseline (speedup 1.0000x reference)
#include <cuda_runtime.h>
#include <cuda_bf16.h>
#include <cstdint>

#define T_LEN      131072
#define N_ST       256
#define ROWS_CHUNK 32
#define CBUF_BYTES 32768                 // 32 cost rows x 1KB
#define NCHUNK     (T_LEN / ROWS_CHUNK)  // 4096
#define UBUF_BYTES 32768                 // 64 u slots x 512B (two 16KB halves)
#define SMEM_TOTAL (3 * CBUF_BYTES + UBUF_BYTES + 128)
#define FLT_MIN_N  1.17549435e-38f

static __device__ float g_cost[(size_t)(T_LEN + 64) * N_ST];
static __device__ float g_u[(size_t)(T_LEN + 1) * 128];

// ---------------------------------------------------------------------------
// Phase A: parallel likelihoods (validated R6: FTZ emulation is load-bearing).
// ---------------------------------------------------------------------------
__global__ void __launch_bounds__(256) va_cost_kernel(const float* __restrict__ rx,
                                                      const float* __restrict__ h,
                                                      float* __restrict__ out) {
    __shared__ float sp[N_ST];
    __shared__ float hs[8];
    const int tid = threadIdx.x;
    if (tid < 8) hs[tid] = h[tid];
    __syncthreads();
    {
        float acc = 0.0f;
#pragma unroll
        for (int j = 0; j < 8; ++j) {
            float sym = ((tid >> (7 - j)) & 1) ? -1.0f : 1.0f;
            acc += sym * hs[j];
        }
        sp[tid] = acc;
    }
    __syncthreads();

    const int lane = tid & 31;
    const int t    = blockIdx.x * 8 + (tid >> 5);
    const float r  = rx[t];

    float p[8];
    float acc = 0.0f;
#pragma unroll
    for (int k = 0; k < 8; ++k) {
        float d = r - sp[lane + 32 * k];
        float a = (-(d * d)) / 0.2f;
        float e = expf(a);
        p[k] = (e < FLT_MIN_N) ? 0.0f : e;   // FTZ
        acc += p[k];
    }
#pragma unroll
    for (int off = 16; off > 0; off >>= 1)
        acc += __shfl_down_sync(0xffffffffu, acc, off);
    const float S = __shfl_sync(0xffffffffu, acc, 0);

    float bv = -1.0f; int bi = 0;
#pragma unroll
    for (int k = 0; k < 8; ++k) {
        float q = __fdiv_rn(p[k], S);
        q = (q < FLT_MIN_N) ? 0.0f : q;      // FTZ
        int s = lane + 32 * k;
        if (q > bv) { bv = q; bi = s; }
        g_cost[(size_t)t * N_ST + s] = -logf(q);
    }
#pragma unroll
    for (int off = 16; off > 0; off >>= 1) {
        float ov = __shfl_xor_sync(0xffffffffu, bv, off);
        int   oi = __shfl_xor_sync(0xffffffffu, bi, off);
        if (ov > bv || (ov == bv && oi < bi)) { bv = ov; bi = oi; }
    }

    if (lane == 0) {
        out[T_LEN + t]     = (float)(bi & 1);
        out[2 * T_LEN + t] = bv;
    }
}

// --- asm helpers ------------------------------------------------------------
__device__ __forceinline__ void st_rel(int* p, int v) {
    asm volatile("st.release.cta.shared.b32 [%0], %1;"
                 :: "r"((unsigned)__cvta_generic_to_shared(p)), "r"(v) : "memory");
}
__device__ __forceinline__ int ld_acq(int* p) {
    int v;
    asm volatile("ld.acquire.cta.shared.b32 %0, [%1];"
                 : "=r"(v) : "r"((unsigned)__cvta_generic_to_shared(p)) : "memory");
    return v;
}
__device__ __forceinline__ void mbar_init(unsigned a, unsigned cnt) {
    asm volatile("mbarrier.init.shared.b64 [%0], %1;" :: "r"(a), "r"(cnt) : "memory");
}
__device__ __forceinline__ void mbar_expect_tx(unsigned a, unsigned bytes) {
    asm volatile("mbarrier.arrive.expect_tx.shared.b64 _, [%0], %1;"
                 :: "r"(a), "r"(bytes) : "memory");
}
__device__ __forceinline__ void mbar_wait(unsigned a, int par) {
    asm volatile(
        "{\n\t.reg .pred P;\n"
        "W%=:\n\t"
        "mbarrier.try_wait.parity.acquire.cta.shared::cta.b64 P, [%0], %1, 0x989680;\n\t"
        "@!P bra W%=;\n\t}"
        :: "r"(a), "r"(par) : "memory");
}
__device__ __forceinline__ void bulk_g2s(unsigned sdst, const void* gsrc,
                                         unsigned bytes, unsigned mbar) {
    asm volatile("cp.async.bulk.shared::cta.global.mbarrier::complete_tx::bytes "
                 "[%0], [%1], %2, [%3];"
                 :: "r"(sdst), "l"(gsrc), "r"(bytes), "r"(mbar) : "memory");
}

// ---------------------------------------------------------------------------
// Phase B: fused 2-step trellis, smem exchange, one __syncwarp per 2 steps.
// Bit-exactness: fmin(x,y)+z == fmin(rnd(x+z),rnd(y+z)) by monotone rounding,
// so x_k = rnd(u+c_t), y = pair-mins (== u_{t+1}, exported), z = rnd(y+c_{t+1}),
// out = pair-mins (== u_{t+2}) reproduces the reference step-by-step bits.
// Layout: lane L owns outputs i = 4L..4L+3. Slot(u_t) = ((t-1) & 63) * 512B
// in ubuf (u_0 pre-seeded in slot 63). Lane-constant offsets:
//   u reads:  bytes (64L mod 512) + 0..63   of slot(u_t)      (4x LDS.128)
//   c_t:      bytes (64L mod 1024) + 0..63  of cost row t     (4x LDS.128)
//   c_{t+1}:  bytes 32L + 0..31             of cost row t+1   (2x LDS.128)
//   y export: bytes 32*(L&15) + 0..31       of slot(u_{t+1})  (2x STS.128,
//             upper half-warp writes identical data to same addr — benign)
//   out:      bytes 16L                     of slot(u_{t+2})  (1x STS.128)
// warp 1: flushes 16KB u halves (32 slots) to g_u via cp.async.bulk S->G.
// ---------------------------------------------------------------------------
__global__ void __launch_bounds__(64) va_viterbi_kernel() {
    extern __shared__ char smem[];
    char* cbuf = smem;                       // 3 x 32KB cost buffers
    char* ubuf = smem + 3 * CBUF_BYTES;      // 64 x 512B u slots
    char* ctrl = ubuf + UBUF_BYTES;
    int*  prod = (int*)(ctrl + 64);
    int*  done = (int*)(ctrl + 96);
    const unsigned mb0 = (unsigned)__cvta_generic_to_shared(ctrl);

    const int tid  = threadIdx.x;
    const int lane = tid & 31;
    const int warp = tid >> 5;

    if (tid == 0) {
        mbar_init(mb0, 1); mbar_init(mb0 + 8, 1); mbar_init(mb0 + 16, 1);
        *prod = 0; *done = -1;
    }
    __syncthreads();

    if (warp == 0) {
        // u_0 = zeros into slot 63
        *(float4*)(ubuf + 63 * 512 + lane * 16) = make_float4(0.f, 0.f, 0.f, 0.f);
        if (lane == 0) {
#pragma unroll
            for (int b = 0; b < 3; ++b) {
                mbar_expect_tx(mb0 + b * 8, CBUF_BYTES);
                bulk_g2s((unsigned)__cvta_generic_to_shared(cbuf + b * CBUF_BYTES),
                         g_cost + (size_t)b * ROWS_CHUNK * N_ST, CBUF_BYTES, mb0 + b * 8);
            }
        }

        const unsigned u_rd  = (unsigned)((64 * lane) & 511);
        const unsigned ct_rd = (unsigned)((64 * lane) & 1023);
        const unsigned cn_rd = (unsigned)(32 * lane);
        const unsigned y_wr  = (unsigned)(32 * (lane & 15));
        const unsigned o_wr  = (unsigned)(16 * lane);

        for (int c = 0; c < NCHUNK; ++c) {
            const int b   = c % 3;
            const int par = (c / 3) & 1;
            mbar_wait(mb0 + b * 8, par);          // cost chunk resident
            while (ld_acq(done) < c - 2) { }      // our half free to overwrite

            const char* crow = cbuf + b * CBUF_BYTES;
            int t = 32 * c;
#pragma unroll 4
            for (int j = 0; j < 16; ++j, t += 2) {
                __syncwarp();
                const char* up = ubuf + (unsigned)(((t - 1) & 63) * 512) + u_rd;
                float4 U0 = *(const float4*)(up);
                float4 U1 = *(const float4*)(up + 16);
                float4 U2 = *(const float4*)(up + 32);
                float4 U3 = *(const float4*)(up + 48);
                const char* cp = crow + 2 * j * 1024 + ct_rd;
                float4 C0 = *(const float4*)(cp);
                float4 C1 = *(const float4*)(cp + 16);
                float4 C2 = *(const float4*)(cp + 32);
                float4 C3 = *(const float4*)(cp + 48);
                const char* np = crow + (2 * j + 1) * 1024 + cn_rd;
                float4 N0 = *(const float4*)(np);
                float4 N1 = *(const float4*)(np + 16);

                // x = u + c_t  (v_t values)
                float y0 = fminf(U0.x + C0.x, U0.y + C0.y);
                float y1 = fminf(U0.z + C0.z, U0.w + C0.w);
                float y2 = fminf(U1.x + C1.x, U1.y + C1.y);
                float y3 = fminf(U1.z + C1.z, U1.w + C1.w);
                float y4 = fminf(U2.x + C2.x, U2.y + C2.y);
                float y5 = fminf(U2.z + C2.z, U2.w + C2.w);
                float y6 = fminf(U3.x + C3.x, U3.y + C3.y);
                float y7 = fminf(U3.z + C3.z, U3.w + C3.w);

                // export u_{t+1} (lanes 16..31 duplicate lanes 0..15 — same data)
                char* yp = ubuf + (unsigned)((t & 63) * 512) + y_wr;
                *(float4*)(yp)      = make_float4(y0, y1, y2, y3);
                *(float4*)(yp + 16) = make_float4(y4, y5, y6, y7);

                // z = y + c_{t+1}, out = pair mins  (u_{t+2})
                float o0 = fminf(y0 + N0.x, y1 + N0.y);
                float o1 = fminf(y2 + N0.z, y3 + N0.w);
                float o2 = fminf(y4 + N1.x, y5 + N1.y);
                float o3 = fminf(y6 + N1.z, y7 + N1.w);
                *(float4*)(ubuf + (unsigned)(((t + 1) & 63) * 512) + o_wr) =
                    make_float4(o0, o1, o2, o3);
            }

            __syncwarp();
            if (lane == 0) {
                st_rel(prod, c + 1);
                if (c + 3 < NCHUNK) {
                    mbar_expect_tx(mb0 + b * 8, CBUF_BYTES);
                    bulk_g2s((unsigned)__cvta_generic_to_shared(cbuf + b * CBUF_BYTES),
                             g_cost + (size_t)(c + 3) * ROWS_CHUNK * N_ST,
                             CBUF_BYTES, mb0 + b * 8);
                }
            }
        }
    } else {
        // warp 1: u_0 row in gmem, then flush halves as they complete
        *(float4*)(g_u + lane * 4) = make_float4(0.f, 0.f, 0.f, 0.f);
        if (lane == 0) {
            for (int c = 0; c < NCHUNK; ++c) {
                while (ld_acq(prod) < c + 1) { }
                asm volatile("fence.proxy.async.shared::cta;" ::: "memory");
                // chunk c wrote u_{32c+1..32c+32} = slots (32c..32c+31)&63
                unsigned ssrc = (unsigned)__cvta_generic_to_shared(
                                    ubuf + ((32 * c) & 63) * 512);
                float* gdst = g_u + (size_t)(c * ROWS_CHUNK + 1) * 128;
                asm volatile("cp.async.bulk.global.shared::cta.bulk_group [%0], [%1], %2;"
                             :: "l"(gdst), "r"(ssrc), "r"(16384u) : "memory");
                asm volatile("cp.async.bulk.commit_group;" ::: "memory");
                asm volatile("cp.async.bulk.wait_group 0;" ::: "memory");
                st_rel(done, c);
            }
        }
    }
}

// ---------------------------------------------------------------------------
// Phase C: parallel bits. One warp per t: bit_t = argmin(u_t) % 2,
// first-index ties (u >= +0, +inf ok -> uint order == float order).
// ---------------------------------------------------------------------------
__global__ void __launch_bounds__(256) va_bits_kernel(float* __restrict__ out) {
    const int lane = threadIdx.x & 31;
    const int t    = blockIdx.x * 8 + (threadIdx.x >> 5);
    const float4 uu = *(const float4*)(g_u + (size_t)t * 128 + lane * 4);
    const int base_li = 4 * lane;
    float lv = uu.x; int li = base_li;
    if (uu.y < lv) { lv = uu.y; li = base_li + 1; }
    if (uu.z < lv) { lv = uu.z; li = base_li + 2; }
    if (uu.w < lv) { lv = uu.w; li = base_li + 3; }
    unsigned lb = __float_as_uint(lv);
    unsigned mv, idx;
    asm volatile("redux.sync.min.u32 %0, %1, 0xffffffff;" : "=r"(mv) : "r"(lb));
    unsigned cand = (lb == mv) ? (unsigned)li : 0xffffffffu;
    asm volatile("redux.sync.min.u32 %0, %1, 0xffffffff;" : "=r"(idx) : "r"(cand));
    if (lane == 0) out[t] = (idx & 1u) ? 1.0f : 0.0f;
}

// ---------------------------------------------------------------------------
// out layout = [detected(T) | confident_bits(T) | confidence(T)], f32.
// ---------------------------------------------------------------------------
extern "C" void kernel_launch(void* const* d_in, const int* in_sizes, int n_in,
                              void* d_out, int out_size) {
    const float* rx = (const float*)d_in[0];
    const float* h  = (const float*)d_in[1];
    if (n_in >= 2 && in_sizes[0] == 8) {   // defensive: inputs swapped
        rx = (const float*)d_in[1];
        h  = (const float*)d_in[0];
    }
    float* out = (float*)d_out;
    cudaFuncSetAttribute(va_viterbi_kernel,
                         cudaFuncAttributeMaxDynamicSharedMemorySize, SMEM_TOTAL);
    va_cost_kernel<<<T_LEN / 8, 256>>>(rx, h, out);
    va_viterbi_kernel<<<1, 64, SMEM_TOTAL>>>();
    va_bits_kernel<<<T_LEN / 8, 256>>>(out);
}

// round 13
// speedup vs baseline: 1.9202x; 1.9202x over previous
#include <cuda_runtime.h>
#include <cuda_bf16.h>
#include <cstdint>

#define T_LEN      131072
#define T_PAD      131076                // divisible by 36 (=12 groups of 3)
#define N_ST       256
#define ROWS_CHUNK 36
#define CBUF_BYTES (ROWS_CHUNK * 1024)   // 36KB
#define NCHUNK     (T_PAD / ROWS_CHUNK)  // 3641
#define UHALF      (ROWS_CHUNK * 512)    // 18KB (36 u slots)
#define SMEM_TOTAL (3 * CBUF_BYTES + 2 * UHALF + 128)
#define FLT_MIN_N  1.17549435e-38f

// cost rows t (t>=T_LEN stay zero: device globals are zero-initialized)
static __device__ float g_cost[(size_t)(T_PAD + 64) * N_ST];
// u_t[128], t = 0..T_PAD (u_0 = zeros)
static __device__ float g_u[(size_t)(T_PAD + 1) * 128];

// ---------------------------------------------------------------------------
// Phase A: parallel likelihoods (R6-validated FTZ emulation).
// NEW: rows with t % 3 == 1 are stored PERMUTED so the trellis step B reads
// its costs as two contiguous LDS.128:
//   pos(j) = 128*(j>>7) + 4*((j&63)>>1) + 2*((j>>6)&1) + (j&1)
// Rows t % 3 in {0,2} are identity.
// ---------------------------------------------------------------------------
__global__ void __launch_bounds__(256) va_cost_kernel(const float* __restrict__ rx,
                                                      const float* __restrict__ h,
                                                      float* __restrict__ out) {
    __shared__ float sp[N_ST];
    __shared__ float hs[8];
    const int tid = threadIdx.x;
    if (tid < 8) hs[tid] = h[tid];
    __syncthreads();
    {
        float acc = 0.0f;
#pragma unroll
        for (int j = 0; j < 8; ++j) {
            float sym = ((tid >> (7 - j)) & 1) ? -1.0f : 1.0f;
            acc += sym * hs[j];
        }
        sp[tid] = acc;
    }
    __syncthreads();

    const int lane = tid & 31;
    const int t    = blockIdx.x * 8 + (tid >> 5);
    const float r  = rx[t];
    const bool permB = (t % 3) == 1;

    float p[8];
    float acc = 0.0f;
#pragma unroll
    for (int k = 0; k < 8; ++k) {
        float d = r - sp[lane + 32 * k];
        float a = (-(d * d)) / 0.2f;
        float e = expf(a);
        p[k] = (e < FLT_MIN_N) ? 0.0f : e;   // FTZ
        acc += p[k];
    }
#pragma unroll
    for (int off = 16; off > 0; off >>= 1)
        acc += __shfl_down_sync(0xffffffffu, acc, off);
    const float S = __shfl_sync(0xffffffffu, acc, 0);

    float bv = -1.0f; int bi = 0;
#pragma unroll
    for (int k = 0; k < 8; ++k) {
        float q = __fdiv_rn(p[k], S);
        q = (q < FLT_MIN_N) ? 0.0f : q;      // FTZ
        int s = lane + 32 * k;
        if (q > bv) { bv = q; bi = s; }
        int pos = s;
        if (permB) {
            int rr = s & 63;
            pos = 128 * (s >> 7) + 4 * (rr >> 1) + 2 * ((s >> 6) & 1) + (rr & 1);
        }
        g_cost[(size_t)t * N_ST + pos] = -logf(q);
    }
#pragma unroll
    for (int off = 16; off > 0; off >>= 1) {
        float ov = __shfl_xor_sync(0xffffffffu, bv, off);
        int   oi = __shfl_xor_sync(0xffffffffu, bi, off);
        if (ov > bv || (ov == bv && oi < bi)) { bv = ov; bi = oi; }
    }

    if (lane == 0) {
        out[T_LEN + t]     = (float)(bi & 1);
        out[2 * T_LEN + t] = bv;
    }
}

// --- asm helpers ------------------------------------------------------------
__device__ __forceinline__ void st_rel(int* p, int v) {
    asm volatile("st.release.cta.shared.b32 [%0], %1;"
                 :: "r"((unsigned)__cvta_generic_to_shared(p)), "r"(v) : "memory");
}
__device__ __forceinline__ int ld_acq(int* p) {
    int v;
    asm volatile("ld.acquire.cta.shared.b32 %0, [%1];"
                 : "=r"(v) : "r"((unsigned)__cvta_generic_to_shared(p)) : "memory");
    return v;
}
__device__ __forceinline__ void mbar_init(unsigned a, unsigned cnt) {
    asm volatile("mbarrier.init.shared.b64 [%0], %1;" :: "r"(a), "r"(cnt) : "memory");
}
__device__ __forceinline__ void mbar_expect_tx(unsigned a, unsigned bytes) {
    asm volatile("mbarrier.arrive.expect_tx.shared.b64 _, [%0], %1;"
                 :: "r"(a), "r"(bytes) : "memory");
}
__device__ __forceinline__ void mbar_wait(unsigned a, int par) {
    asm volatile(
        "{\n\t.reg .pred P;\n"
        "W%=:\n\t"
        "mbarrier.try_wait.parity.acquire.cta.shared::cta.b64 P, [%0], %1, 0x989680;\n\t"
        "@!P bra W%=;\n\t}"
        :: "r"(a), "r"(par) : "memory");
}
__device__ __forceinline__ void bulk_g2s(unsigned sdst, const void* gsrc,
                                         unsigned bytes, unsigned mbar) {
    asm volatile("cp.async.bulk.shared::cta.global.mbarrier::complete_tx::bytes "
                 "[%0], [%1], %2, [%3];"
                 :: "r"(sdst), "l"(gsrc), "r"(bytes), "r"(mbar) : "memory");
}

// ---------------------------------------------------------------------------
// Phase B: 3-phase trellis, ONE __syncwarp per 3 steps, ZERO SHFL.
//  step A (Q->P, local): out {2L,2L+1,2L+64,2L+65} from u[4L..4L+3]
//  step B (P->S, local): out {L,L+32,L+64,L+96}; costs from permuted row
//  step C (S->Q, exchange): reads u_{t} from step B's canonical smem export
// Every step's arithmetic = min(u[2i%128]+c[2i], u[2i+1%128]+c[2i+1]) bit-exact.
// warp 1 flushes 18KB u halves (36 slots) to g_u via cp.async.bulk S->G.
// ---------------------------------------------------------------------------
__global__ void __launch_bounds__(64) va_viterbi_kernel() {
    extern __shared__ char smem[];
    char* cbuf = smem;                       // 3 x 36KB cost buffers
    char* ubuf = smem + 3 * CBUF_BYTES;      // 2 x 18KB u halves (36 slots each)
    char* ctrl = ubuf + 2 * UHALF;
    int*  prod = (int*)(ctrl + 64);
    int*  done = (int*)(ctrl + 96);
    const unsigned mb0 = (unsigned)__cvta_generic_to_shared(ctrl);

    const int tid  = threadIdx.x;
    const int lane = tid & 31;
    const int warp = tid >> 5;

    if (tid == 0) {
        mbar_init(mb0, 1); mbar_init(mb0 + 8, 1); mbar_init(mb0 + 16, 1);
        *prod = 0; *done = -1;
    }
    __syncthreads();

    if (warp == 0) {
        if (lane == 0) {
#pragma unroll
            for (int b = 0; b < 3; ++b) {
                mbar_expect_tx(mb0 + b * 8, CBUF_BYTES);
                bulk_g2s((unsigned)__cvta_generic_to_shared(cbuf + b * CBUF_BYTES),
                         g_cost + (size_t)b * ROWS_CHUNK * N_ST, CBUF_BYTES, mb0 + b * 8);
            }
        }

        float q0 = 0.f, q1 = 0.f, q2 = 0.f, q3 = 0.f;   // u_0 in Q layout
        const unsigned off16 = (unsigned)(16 * lane);
        const unsigned off8  = (unsigned)(8 * lane);
        const unsigned off4  = (unsigned)(4 * lane);
        const unsigned gath  = (unsigned)((32 * lane) & 511);
        const unsigned off32 = (unsigned)(32 * lane);

        for (int c = 0; c < NCHUNK; ++c) {
            const int b   = c % 3;
            const int par = (c / 3) & 1;
            mbar_wait(mb0 + b * 8, par);          // cost chunk resident
            while (ld_acq(done) < c - 2) { }      // our u half free

            const char* crow = cbuf + b * CBUF_BYTES;
            char*       uh   = ubuf + (c & 1) * UHALF;
#pragma unroll 4
            for (int g = 0; g < 12; ++g) {
                // ---- step A (local): Q -> P ----
                float4 CA = *(const float4*)(crow + off16);
                float4 CB = *(const float4*)(crow + 512 + off16);
                float p0 = fminf(q0 + CA.x, q1 + CA.y);   // u'[2L]
                float p1 = fminf(q2 + CA.z, q3 + CA.w);   // u'[2L+1]
                float p2 = fminf(q0 + CB.x, q1 + CB.y);   // u'[2L+64]
                float p3 = fminf(q2 + CB.z, q3 + CB.w);   // u'[2L+65]
                char* slA = uh + (3 * g) * 512;
                *(float2*)(slA + off8)       = make_float2(p0, p1);
                *(float2*)(slA + 256 + off8) = make_float2(p2, p3);

                // ---- step B (local): P -> S, permuted costs ----
                float4 DA = *(const float4*)(crow + 1024 + off16);
                float4 DB = *(const float4*)(crow + 1536 + off16);
                float s0 = fminf(p0 + DA.x, p1 + DA.y);   // u''[L]
                float s1 = fminf(p2 + DA.z, p3 + DA.w);   // u''[L+32]
                float s2 = fminf(p0 + DB.x, p1 + DB.y);   // u''[L+64]
                float s3 = fminf(p2 + DB.z, p3 + DB.w);   // u''[L+96]
                char* slB = uh + (3 * g + 1) * 512;
                *(float*)(slB + off4)        = s0;
                *(float*)(slB + 128 + off4)  = s1;
                *(float*)(slB + 256 + off4)  = s2;
                *(float*)(slB + 384 + off4)  = s3;

                __syncwarp();

                // ---- step C (exchange): S -> Q via B's canonical export ----
                float4 G0 = *(const float4*)(slB + gath);        // u''[8L'..+3]
                float4 G1 = *(const float4*)(slB + gath + 16);   // u''[8L'+4..+7]
                float4 EA = *(const float4*)(crow + 2048 + off32);
                float4 EB = *(const float4*)(crow + 2048 + off32 + 16);
                q0 = fminf(G0.x + EA.x, G0.y + EA.y);   // u'''[4L']
                q1 = fminf(G0.z + EA.z, G0.w + EA.w);   // u'''[4L'+1]
                q2 = fminf(G1.x + EB.x, G1.y + EB.y);   // u'''[4L'+2]
                q3 = fminf(G1.z + EB.z, G1.w + EB.w);   // u'''[4L'+3]
                *(float4*)(uh + (3 * g + 2) * 512 + off16) = make_float4(q0, q1, q2, q3);

                crow += 3 * 1024;
            }

            __syncwarp();
            if (lane == 0) {
                st_rel(prod, c + 1);
                if (c + 3 < NCHUNK) {
                    mbar_expect_tx(mb0 + b * 8, CBUF_BYTES);
                    bulk_g2s((unsigned)__cvta_generic_to_shared(cbuf + b * CBUF_BYTES),
                             g_cost + (size_t)(c + 3) * ROWS_CHUNK * N_ST,
                             CBUF_BYTES, mb0 + b * 8);
                }
            }
        }
    } else {
        // warp 1: u_0 row, then flush halves as chunks complete
        *(float4*)(g_u + lane * 4) = make_float4(0.f, 0.f, 0.f, 0.f);
        if (lane == 0) {
            for (int c = 0; c < NCHUNK; ++c) {
                while (ld_acq(prod) < c + 1) { }
                asm volatile("fence.proxy.async.shared::cta;" ::: "memory");
                unsigned ssrc = (unsigned)__cvta_generic_to_shared(ubuf + (c & 1) * UHALF);
                float* gdst = g_u + (size_t)(c * ROWS_CHUNK + 1) * 128;
                asm volatile("cp.async.bulk.global.shared::cta.bulk_group [%0], [%1], %2;"
                             :: "l"(gdst), "r"(ssrc), "r"((unsigned)UHALF) : "memory");
                asm volatile("cp.async.bulk.commit_group;" ::: "memory");
                asm volatile("cp.async.bulk.wait_group 0;" ::: "memory");
                st_rel(done, c);
            }
        }
    }
}

// ---------------------------------------------------------------------------
// Phase C: parallel bits. One warp per t: bit_t = argmin(u_t) % 2,
// first-index ties (u >= +0, +inf ok -> uint order == float order).
// ---------------------------------------------------------------------------
__global__ void __launch_bounds__(256) va_bits_kernel(float* __restrict__ out) {
    const int lane = threadIdx.x & 31;
    const int t    = blockIdx.x * 8 + (threadIdx.x >> 5);
    const float4 uu = *(const float4*)(g_u + (size_t)t * 128 + lane * 4);
    const int base_li = 4 * lane;
    float lv = uu.x; int li = base_li;
    if (uu.y < lv) { lv = uu.y; li = base_li + 1; }
    if (uu.z < lv) { lv = uu.z; li = base_li + 2; }
    if (uu.w < lv) { lv = uu.w; li = base_li + 3; }
    unsigned lb = __float_as_uint(lv);
    unsigned mv, idx;
    asm volatile("redux.sync.min.u32 %0, %1, 0xffffffff;" : "=r"(mv) : "r"(lb));
    unsigned cand = (lb == mv) ? (unsigned)li : 0xffffffffu;
    asm volatile("redux.sync.min.u32 %0, %1, 0xffffffff;" : "=r"(idx) : "r"(cand));
    if (lane == 0) out[t] = (idx & 1u) ? 1.0f : 0.0f;
}

// ---------------------------------------------------------------------------
// out layout = [detected(T) | confident_bits(T) | confidence(T)], f32.
// ---------------------------------------------------------------------------
extern "C" void kernel_launch(void* const* d_in, const int* in_sizes, int n_in,
                              void* d_out, int out_size) {
    const float* rx = (const float*)d_in[0];
    const float* h  = (const float*)d_in[1];
    if (n_in >= 2 && in_sizes[0] == 8) {   // defensive: inputs swapped
        rx = (const float*)d_in[1];
        h  = (const float*)d_in[0];
    }
    float* out = (float*)d_out;
    cudaFuncSetAttribute(va_viterbi_kernel,
                         cudaFuncAttributeMaxDynamicSharedMemorySize, SMEM_TOTAL);
    va_cost_kernel<<<T_LEN / 8, 256>>>(rx, h, out);
    va_viterbi_kernel<<<1, 64, SMEM_TOTAL>>>();
    va_bits_kernel<<<T_LEN / 8, 256>>>(out);
}

// round 14
// speedup vs baseline: 2.3458x; 1.2216x over previous
#include <cuda_runtime.h>
#include <cuda_bf16.h>
#include <cstdint>

#define T_LEN      131072
#define T_PAD      131076                // divisible by 36
#define N_ST       256
#define ROWS_CHUNK 36
#define CBUF_BYTES (ROWS_CHUNK * 1024)   // 36KB
#define NCHUNK     (T_PAD / ROWS_CHUNK)  // 3641
#define UHALF      12288                 // 24 u slots (12 groups x {B,C}) x 512B
#define SMEM_TOTAL (3 * CBUF_BYTES + 2 * UHALF + 128)
#define FLT_MIN_N  1.17549435e-38f

// cost rows t (t>=T_LEN stay zero: device globals zero-init)
static __device__ float g_cost[(size_t)(T_PAD + 64) * N_ST];
// compacted u rows: row 0 = u_0; row 2g+1 = u_{3g+2}; row 2g+2 = u_{3g+3}
// (so u_{3m} lives at row 2m). 87385 rows.
static __device__ float g_u2[(size_t)(1 + 2 * (NCHUNK * 12)) * 128];

// bit-exact add via FFMA-imm (rt_SMSP=1 vs FADD's 2); u*1.0+c rounds == u+c
__device__ __forceinline__ float addi(float a, float b) {
    float r;
    asm("fma.rn.f32 %0, %1, 0f3F800000, %2;" : "=f"(r) : "f"(a), "f"(b));
    return r;
}

// ---------------------------------------------------------------------------
// Phase A: parallel likelihoods (R6-validated FTZ emulation). Rows t%3==1
// stored permuted for trellis step B:
//   pos(j) = 128*(j>>7) + 4*((j&63)>>1) + 2*((j>>6)&1) + (j&1)
// ---------------------------------------------------------------------------
__global__ void __launch_bounds__(256) va_cost_kernel(const float* __restrict__ rx,
                                                      const float* __restrict__ h,
                                                      float* __restrict__ out) {
    __shared__ float sp[N_ST];
    __shared__ float hs[8];
    const int tid = threadIdx.x;
    if (tid < 8) hs[tid] = h[tid];
    __syncthreads();
    {
        float acc = 0.0f;
#pragma unroll
        for (int j = 0; j < 8; ++j) {
            float sym = ((tid >> (7 - j)) & 1) ? -1.0f : 1.0f;
            acc += sym * hs[j];
        }
        sp[tid] = acc;
    }
    __syncthreads();

    const int lane = tid & 31;
    const int t    = blockIdx.x * 8 + (tid >> 5);
    const float r  = rx[t];
    const bool permB = (t % 3) == 1;

    float p[8];
    float acc = 0.0f;
#pragma unroll
    for (int k = 0; k < 8; ++k) {
        float d = r - sp[lane + 32 * k];
        float a = (-(d * d)) / 0.2f;
        float e = expf(a);
        p[k] = (e < FLT_MIN_N) ? 0.0f : e;   // FTZ
        acc += p[k];
    }
#pragma unroll
    for (int off = 16; off > 0; off >>= 1)
        acc += __shfl_down_sync(0xffffffffu, acc, off);
    const float S = __shfl_sync(0xffffffffu, acc, 0);

    float bv = -1.0f; int bi = 0;
#pragma unroll
    for (int k = 0; k < 8; ++k) {
        float q = __fdiv_rn(p[k], S);
        q = (q < FLT_MIN_N) ? 0.0f : q;      // FTZ
        int s = lane + 32 * k;
        if (q > bv) { bv = q; bi = s; }
        int pos = s;
        if (permB) {
            int rr = s & 63;
            pos = 128 * (s >> 7) + 4 * (rr >> 1) + 2 * ((s >> 6) & 1) + (rr & 1);
        }
        g_cost[(size_t)t * N_ST + pos] = -logf(q);
    }
#pragma unroll
    for (int off = 16; off > 0; off >>= 1) {
        float ov = __shfl_xor_sync(0xffffffffu, bv, off);
        int   oi = __shfl_xor_sync(0xffffffffu, bi, off);
        if (ov > bv || (ov == bv && oi < bi)) { bv = ov; bi = oi; }
    }

    if (lane == 0) {
        out[T_LEN + t]     = (float)(bi & 1);
        out[2 * T_LEN + t] = bv;
    }
}

// --- asm helpers ------------------------------------------------------------
__device__ __forceinline__ void st_rel(int* p, int v) {
    asm volatile("st.release.cta.shared.b32 [%0], %1;"
                 :: "r"((unsigned)__cvta_generic_to_shared(p)), "r"(v) : "memory");
}
__device__ __forceinline__ int ld_acq(int* p) {
    int v;
    asm volatile("ld.acquire.cta.shared.b32 %0, [%1];"
                 : "=r"(v) : "r"((unsigned)__cvta_generic_to_shared(p)) : "memory");
    return v;
}
__device__ __forceinline__ void mbar_init(unsigned a, unsigned cnt) {
    asm volatile("mbarrier.init.shared.b64 [%0], %1;" :: "r"(a), "r"(cnt) : "memory");
}
__device__ __forceinline__ void mbar_expect_tx(unsigned a, unsigned bytes) {
    asm volatile("mbarrier.arrive.expect_tx.shared.b64 _, [%0], %1;"
                 :: "r"(a), "r"(bytes) : "memory");
}
__device__ __forceinline__ void mbar_wait(unsigned a, int par) {
    asm volatile(
        "{\n\t.reg .pred P;\n"
        "W%=:\n\t"
        "mbarrier.try_wait.parity.acquire.cta.shared::cta.b64 P, [%0], %1, 0x989680;\n\t"
        "@!P bra W%=;\n\t}"
        :: "r"(a), "r"(par) : "memory");
}
__device__ __forceinline__ void bulk_g2s(unsigned sdst, const void* gsrc,
                                         unsigned bytes, unsigned mbar) {
    asm volatile("cp.async.bulk.shared::cta.global.mbarrier::complete_tx::bytes "
                 "[%0], [%1], %2, [%3];"
                 :: "r"(sdst), "l"(gsrc), "r"(bytes), "r"(mbar) : "memory");
}

// ---------------------------------------------------------------------------
// Phase B: 3-phase trellis (exchange once per 3 steps), FFMA-imm adds,
// exports only u_{3g+2} (slB: doubles as the exchange) and u_{3g+3} (slC).
// u_{3g+1} is recomputed by the bits kernel. warp 1 flushes 12KB halves.
// ---------------------------------------------------------------------------
__global__ void __launch_bounds__(64) va_viterbi_kernel() {
    extern __shared__ char smem[];
    char* cbuf = smem;                       // 3 x 36KB cost buffers
    char* ubuf = smem + 3 * CBUF_BYTES;      // 2 x 12KB u halves (24 slots each)
    char* ctrl = ubuf + 2 * UHALF;
    int*  prod = (int*)(ctrl + 64);
    int*  done = (int*)(ctrl + 96);
    const unsigned mb0 = (unsigned)__cvta_generic_to_shared(ctrl);

    const int tid  = threadIdx.x;
    const int lane = tid & 31;
    const int warp = tid >> 5;

    if (tid == 0) {
        mbar_init(mb0, 1); mbar_init(mb0 + 8, 1); mbar_init(mb0 + 16, 1);
        *prod = 0; *done = -1;
    }
    __syncthreads();

    if (warp == 0) {
        if (lane == 0) {
#pragma unroll
            for (int b = 0; b < 3; ++b) {
                mbar_expect_tx(mb0 + b * 8, CBUF_BYTES);
                bulk_g2s((unsigned)__cvta_generic_to_shared(cbuf + b * CBUF_BYTES),
                         g_cost + (size_t)b * ROWS_CHUNK * N_ST, CBUF_BYTES, mb0 + b * 8);
            }
        }

        float q0 = 0.f, q1 = 0.f, q2 = 0.f, q3 = 0.f;   // u_0 in Q layout
        const unsigned off16 = (unsigned)(16 * lane);
        const unsigned off4  = (unsigned)(4 * lane);
        const unsigned gath  = (unsigned)((32 * lane) & 511);
        const unsigned off32 = (unsigned)(32 * lane);

        for (int c = 0; c < NCHUNK; ++c) {
            const int b   = c % 3;
            const int par = (c / 3) & 1;
            mbar_wait(mb0 + b * 8, par);          // cost chunk resident
            while (ld_acq(done) < c - 2) { }      // our u half free

            const char* crow0 = cbuf + b * CBUF_BYTES;
            char*       uh    = ubuf + (c & 1) * UHALF;
#pragma unroll
            for (int g = 0; g < 12; ++g) {
                const char* crow = crow0 + g * 3072;
                // ---- step A (local): Q -> P ----
                float4 CA = *(const float4*)(crow + off16);
                float4 CB = *(const float4*)(crow + 512 + off16);
                float p0 = fminf(addi(q0, CA.x), addi(q1, CA.y));   // u'[2L]
                float p1 = fminf(addi(q2, CA.z), addi(q3, CA.w));   // u'[2L+1]
                float p2 = fminf(addi(q0, CB.x), addi(q1, CB.y));   // u'[2L+64]
                float p3 = fminf(addi(q2, CB.z), addi(q3, CB.w));   // u'[2L+65]

                // ---- step B (local): P -> S, permuted costs ----
                float4 DA = *(const float4*)(crow + 1024 + off16);
                float4 DB = *(const float4*)(crow + 1536 + off16);
                float s0 = fminf(addi(p0, DA.x), addi(p1, DA.y));   // u''[L]
                float s1 = fminf(addi(p2, DA.z), addi(p3, DA.w));   // u''[L+32]
                float s2 = fminf(addi(p0, DB.x), addi(p1, DB.y));   // u''[L+64]
                float s3 = fminf(addi(p2, DB.z), addi(p3, DB.w));   // u''[L+96]
                char* slB = uh + g * 1024;           // export u_{3g+2} (canonical)
                *(float*)(slB + off4)        = s0;
                *(float*)(slB + 128 + off4)  = s1;
                *(float*)(slB + 256 + off4)  = s2;
                *(float*)(slB + 384 + off4)  = s3;

                __syncwarp();

                // ---- step C (exchange): S -> Q via slB ----
                float4 G0 = *(const float4*)(slB + gath);        // u''[8L'..+3]
                float4 G1 = *(const float4*)(slB + gath + 16);   // u''[8L'+4..+7]
                float4 EA = *(const float4*)(crow + 2048 + off32);
                float4 EB = *(const float4*)(crow + 2048 + off32 + 16);
                q0 = fminf(addi(G0.x, EA.x), addi(G0.y, EA.y));   // u'''[4L']
                q1 = fminf(addi(G0.z, EA.z), addi(G0.w, EA.w));
                q2 = fminf(addi(G1.x, EB.x), addi(G1.y, EB.y));
                q3 = fminf(addi(G1.z, EB.z), addi(G1.w, EB.w));
                *(float4*)(slB + 512 + off16) = make_float4(q0, q1, q2, q3); // u_{3g+3}
            }

            __syncwarp();
            if (lane == 0) {
                st_rel(prod, c + 1);
                if (c + 3 < NCHUNK) {
                    mbar_expect_tx(mb0 + b * 8, CBUF_BYTES);
                    bulk_g2s((unsigned)__cvta_generic_to_shared(cbuf + b * CBUF_BYTES),
                             g_cost + (size_t)(c + 3) * ROWS_CHUNK * N_ST,
                             CBUF_BYTES, mb0 + b * 8);
                }
            }
        }
    } else {
        // warp 1: u_0 row, then flush 12KB halves (24 rows/chunk) to g_u2
        *(float4*)(g_u2 + lane * 4) = make_float4(0.f, 0.f, 0.f, 0.f);
        if (lane == 0) {
            for (int c = 0; c < NCHUNK; ++c) {
                while (ld_acq(prod) < c + 1) { }
                asm volatile("fence.proxy.async.shared::cta;" ::: "memory");
                unsigned ssrc = (unsigned)__cvta_generic_to_shared(ubuf + (c & 1) * UHALF);
                float* gdst = g_u2 + (size_t)(1 + 24 * c) * 128;
                asm volatile("cp.async.bulk.global.shared::cta.bulk_group [%0], [%1], %2;"
                             :: "l"(gdst), "r"(ssrc), "r"((unsigned)UHALF) : "memory");
                asm volatile("cp.async.bulk.commit_group;" ::: "memory");
                asm volatile("cp.async.bulk.wait_group 0;" ::: "memory");
                st_rel(done, c);
            }
        }
    }
}

// ---------------------------------------------------------------------------
// Phase C: parallel bits. One warp per t.
//  t%3==0: u_t = g_u2 row 2*(t/3)
//  t%3==2: u_t = g_u2 row 2*((t-2)/3)+1
//  t%3==1: recompute u_t from u_{t-1} (row 2*((t-1)/3)) + cost row t-1
//          (identity layout), same rnd(a+b)/fminf arithmetic -> bit-exact.
// Then bit = argmin(u_t) % 2, first-index ties.
// ---------------------------------------------------------------------------
__global__ void __launch_bounds__(256) va_bits_kernel(float* __restrict__ out) {
    const int lane = threadIdx.x & 31;
    const int t    = blockIdx.x * 8 + (threadIdx.x >> 5);
    const int r    = t % 3;
    const int base_li = 4 * lane;

    float4 uu;
    if (r == 1) {
        const float* urow = g_u2 + (size_t)(2 * ((t - 1) / 3)) * 128;
        const float* crow = g_cost + (size_t)(t - 1) * N_ST;
        float4 U0 = *(const float4*)(urow + ((8 * lane) & 127));
        float4 U1 = *(const float4*)(urow + ((8 * lane + 4) & 127));
        float4 C0 = *(const float4*)(crow + 8 * lane);
        float4 C1 = *(const float4*)(crow + 8 * lane + 4);
        uu.x = fminf(U0.x + C0.x, U0.y + C0.y);
        uu.y = fminf(U0.z + C0.z, U0.w + C0.w);
        uu.z = fminf(U1.x + C1.x, U1.y + C1.y);
        uu.w = fminf(U1.z + C1.z, U1.w + C1.w);
    } else {
        const int row = (r == 0) ? 2 * (t / 3) : 2 * ((t - 2) / 3) + 1;
        uu = *(const float4*)(g_u2 + (size_t)row * 128 + lane * 4);
    }

    float lv = uu.x; int li = base_li;
    if (uu.y < lv) { lv = uu.y; li = base_li + 1; }
    if (uu.z < lv) { lv = uu.z; li = base_li + 2; }
    if (uu.w < lv) { lv = uu.w; li = base_li + 3; }
    unsigned lb = __float_as_uint(lv);
    unsigned mv, idx;
    asm volatile("redux.sync.min.u32 %0, %1, 0xffffffff;" : "=r"(mv) : "r"(lb));
    unsigned cand = (lb == mv) ? (unsigned)li : 0xffffffffu;
    asm volatile("redux.sync.min.u32 %0, %1, 0xffffffff;" : "=r"(idx) : "r"(cand));
    if (lane == 0) out[t] = (idx & 1u) ? 1.0f : 0.0f;
}

// ---------------------------------------------------------------------------
// out layout = [detected(T) | confident_bits(T) | confidence(T)], f32.
// ---------------------------------------------------------------------------
extern "C" void kernel_launch(void* const* d_in, const int* in_sizes, int n_in,
                              void* d_out, int out_size) {
    const float* rx = (const float*)d_in[0];
    const float* h  = (const float*)d_in[1];
    if (n_in >= 2 && in_sizes[0] == 8) {   // defensive: inputs swapped
        rx = (const float*)d_in[1];
        h  = (const float*)d_in[0];
    }
    float* out = (float*)d_out;
    cudaFuncSetAttribute(va_viterbi_kernel,
                         cudaFuncAttributeMaxDynamicSharedMemorySize, SMEM_TOTAL);
    va_cost_kernel<<<T_LEN / 8, 256>>>(rx, h, out);
    va_viterbi_kernel<<<1, 64, SMEM_TOTAL>>>();
    va_bits_kernel<<<T_LEN / 8, 256>>>(out);
}

// round 15
// speedup vs baseline: 3.0245x; 1.2893x over previous
#include <cuda_runtime.h>
#include <cuda_bf16.h>
#include <cstdint>

#define T_LEN      131072
#define T_PAD      131076                // divisible by 36
#define N_ST       256
#define ROWS_CHUNK 36
#define CBUF_BYTES (ROWS_CHUNK * 1024)   // 36KB
#define NCHUNK     (T_PAD / ROWS_CHUNK)  // 3641
#define UHALF      6144                  // 12 u slots x 512B per chunk half
#define SMEM_TOTAL (3 * CBUF_BYTES + 2 * UHALF + 128)
#define FLT_MIN_N  1.17549435e-38f

// cost rows t (t>=T_LEN stay zero: device globals zero-init)
static __device__ float g_cost[(size_t)(T_PAD + 64) * N_ST];
// exported u rows: row g = u_{3g+2}, g = 0..NCHUNK*12-1
static __device__ float g_u3[(size_t)(NCHUNK * 12) * 128];

// packed add: (ox,oy) = (a0+b0, a1+b1), each half rn-rounded == scalar FADD
__device__ __forceinline__ void add2(float& ox, float& oy,
                                     float a0, float a1, float b0, float b1) {
    asm("{\n\t.reg .b64 ra, rb, rc;\n\t"
        "mov.b64 ra, {%2, %3};\n\t"
        "mov.b64 rb, {%4, %5};\n\t"
        "add.rn.f32x2 rc, ra, rb;\n\t"
        "mov.b64 {%0, %1}, rc;\n\t}"
        : "=f"(ox), "=f"(oy) : "f"(a0), "f"(a1), "f"(b0), "f"(b1));
}

// ---------------------------------------------------------------------------
// Phase A: parallel likelihoods (R6-validated FTZ emulation). Rows t%3==1
// stored permuted for trellis step B:
//   pos(j) = 128*(j>>7) + 4*((j&63)>>1) + 2*((j>>6)&1) + (j&1)
// ---------------------------------------------------------------------------
__global__ void __launch_bounds__(256) va_cost_kernel(const float* __restrict__ rx,
                                                      const float* __restrict__ h,
                                                      float* __restrict__ out) {
    __shared__ float sp[N_ST];
    __shared__ float hs[8];
    const int tid = threadIdx.x;
    if (tid < 8) hs[tid] = h[tid];
    __syncthreads();
    {
        float acc = 0.0f;
#pragma unroll
        for (int j = 0; j < 8; ++j) {
            float sym = ((tid >> (7 - j)) & 1) ? -1.0f : 1.0f;
            acc += sym * hs[j];
        }
        sp[tid] = acc;
    }
    __syncthreads();

    const int lane = tid & 31;
    const int t    = blockIdx.x * 8 + (tid >> 5);
    const float r  = rx[t];
    const bool permB = (t % 3) == 1;

    float p[8];
    float acc = 0.0f;
#pragma unroll
    for (int k = 0; k < 8; ++k) {
        float d = r - sp[lane + 32 * k];
        float a = (-(d * d)) / 0.2f;
        float e = expf(a);
        p[k] = (e < FLT_MIN_N) ? 0.0f : e;   // FTZ
        acc += p[k];
    }
#pragma unroll
    for (int off = 16; off > 0; off >>= 1)
        acc += __shfl_down_sync(0xffffffffu, acc, off);
    const float S = __shfl_sync(0xffffffffu, acc, 0);

    float bv = -1.0f; int bi = 0;
#pragma unroll
    for (int k = 0; k < 8; ++k) {
        float q = __fdiv_rn(p[k], S);
        q = (q < FLT_MIN_N) ? 0.0f : q;      // FTZ
        int s = lane + 32 * k;
        if (q > bv) { bv = q; bi = s; }
        int pos = s;
        if (permB) {
            int rr = s & 63;
            pos = 128 * (s >> 7) + 4 * (rr >> 1) + 2 * ((s >> 6) & 1) + (rr & 1);
        }
        g_cost[(size_t)t * N_ST + pos] = -logf(q);
    }
#pragma unroll
    for (int off = 16; off > 0; off >>= 1) {
        float ov = __shfl_xor_sync(0xffffffffu, bv, off);
        int   oi = __shfl_xor_sync(0xffffffffu, bi, off);
        if (ov > bv || (ov == bv && oi < bi)) { bv = ov; bi = oi; }
    }

    if (lane == 0) {
        out[T_LEN + t]     = (float)(bi & 1);
        out[2 * T_LEN + t] = bv;
    }
}

// --- asm helpers ------------------------------------------------------------
__device__ __forceinline__ void st_rel(int* p, int v) {
    asm volatile("st.release.cta.shared.b32 [%0], %1;"
                 :: "r"((unsigned)__cvta_generic_to_shared(p)), "r"(v) : "memory");
}
__device__ __forceinline__ int ld_acq(int* p) {
    int v;
    asm volatile("ld.acquire.cta.shared.b32 %0, [%1];"
                 : "=r"(v) : "r"((unsigned)__cvta_generic_to_shared(p)) : "memory");
    return v;
}
__device__ __forceinline__ void mbar_init(unsigned a, unsigned cnt) {
    asm volatile("mbarrier.init.shared.b64 [%0], %1;" :: "r"(a), "r"(cnt) : "memory");
}
__device__ __forceinline__ void mbar_expect_tx(unsigned a, unsigned bytes) {
    asm volatile("mbarrier.arrive.expect_tx.shared.b64 _, [%0], %1;"
                 :: "r"(a), "r"(bytes) : "memory");
}
__device__ __forceinline__ void mbar_wait(unsigned a, int par) {
    asm volatile(
        "{\n\t.reg .pred P;\n"
        "W%=:\n\t"
        "mbarrier.try_wait.parity.acquire.cta.shared::cta.b64 P, [%0], %1, 0x989680;\n\t"
        "@!P bra W%=;\n\t}"
        :: "r"(a), "r"(par) : "memory");
}
__device__ __forceinline__ void bulk_g2s(unsigned sdst, const void* gsrc,
                                         unsigned bytes, unsigned mbar) {
    asm volatile("cp.async.bulk.shared::cta.global.mbarrier::complete_tx::bytes "
                 "[%0], [%1], %2, [%3];"
                 :: "r"(sdst), "l"(gsrc), "r"(bytes), "r"(mbar) : "memory");
}

// ---------------------------------------------------------------------------
// Phase B: 3-phase trellis (exchange once per 3 steps), packed f32x2 adds,
// exports ONLY u_{3g+2} (the slB exchange write). u_{3g+1} and u_{3g+3}
// are recomputed by the bits kernel. warp 1 flushes 6KB halves.
// ---------------------------------------------------------------------------
__global__ void __launch_bounds__(64) va_viterbi_kernel() {
    extern __shared__ char smem[];
    char* cbuf = smem;                       // 3 x 36KB cost buffers
    char* ubuf = smem + 3 * CBUF_BYTES;      // 2 x 6KB u halves (12 slots each)
    char* ctrl = ubuf + 2 * UHALF;
    int*  prod = (int*)(ctrl + 64);
    int*  done = (int*)(ctrl + 96);
    const unsigned mb0 = (unsigned)__cvta_generic_to_shared(ctrl);

    const int tid  = threadIdx.x;
    const int lane = tid & 31;
    const int warp = tid >> 5;

    if (tid == 0) {
        mbar_init(mb0, 1); mbar_init(mb0 + 8, 1); mbar_init(mb0 + 16, 1);
        *prod = 0; *done = -1;
    }
    __syncthreads();

    if (warp == 0) {
        if (lane == 0) {
#pragma unroll
            for (int b = 0; b < 3; ++b) {
                mbar_expect_tx(mb0 + b * 8, CBUF_BYTES);
                bulk_g2s((unsigned)__cvta_generic_to_shared(cbuf + b * CBUF_BYTES),
                         g_cost + (size_t)b * ROWS_CHUNK * N_ST, CBUF_BYTES, mb0 + b * 8);
            }
        }

        float q0 = 0.f, q1 = 0.f, q2 = 0.f, q3 = 0.f;   // u_0 in Q layout
        const unsigned off16 = (unsigned)(16 * lane);
        const unsigned off4  = (unsigned)(4 * lane);
        const unsigned gath  = (unsigned)((32 * lane) & 511);
        const unsigned off32 = (unsigned)(32 * lane);

        for (int c = 0; c < NCHUNK; ++c) {
            const int b   = c % 3;
            const int par = (c / 3) & 1;
            mbar_wait(mb0 + b * 8, par);          // cost chunk resident
            while (ld_acq(done) < c - 2) { }      // our u half free

            const char* crow0 = cbuf + b * CBUF_BYTES;
            char*       uh    = ubuf + (c & 1) * UHALF;
#pragma unroll
            for (int g = 0; g < 12; ++g) {
                const char* crow = crow0 + g * 3072;
                float4 CA = *(const float4*)(crow + off16);
                float4 CB = *(const float4*)(crow + 512 + off16);
                float4 DA = *(const float4*)(crow + 1024 + off16);
                float4 DB = *(const float4*)(crow + 1536 + off16);
                float4 EA = *(const float4*)(crow + 2048 + off32);      // hoisted
                float4 EB = *(const float4*)(crow + 2048 + off32 + 16); // hoisted

                // ---- step A (local): Q -> P ----
                float t0, t1, p0, p1, p2, p3;
                add2(t0, t1, q0, q1, CA.x, CA.y); p0 = fminf(t0, t1);   // u'[2L]
                add2(t0, t1, q2, q3, CA.z, CA.w); p1 = fminf(t0, t1);   // u'[2L+1]
                add2(t0, t1, q0, q1, CB.x, CB.y); p2 = fminf(t0, t1);   // u'[2L+64]
                add2(t0, t1, q2, q3, CB.z, CB.w); p3 = fminf(t0, t1);   // u'[2L+65]

                // ---- step B (local): P -> S, permuted costs ----
                float s0, s1, s2, s3;
                add2(t0, t1, p0, p1, DA.x, DA.y); s0 = fminf(t0, t1);   // u''[L]
                add2(t0, t1, p2, p3, DA.z, DA.w); s1 = fminf(t0, t1);   // u''[L+32]
                add2(t0, t1, p0, p1, DB.x, DB.y); s2 = fminf(t0, t1);   // u''[L+64]
                add2(t0, t1, p2, p3, DB.z, DB.w); s3 = fminf(t0, t1);   // u''[L+96]
                char* slB = uh + g * 512;           // canonical export u_{3g+2}
                *(float*)(slB + off4)        = s0;
                *(float*)(slB + 128 + off4)  = s1;
                *(float*)(slB + 256 + off4)  = s2;
                *(float*)(slB + 384 + off4)  = s3;

                __syncwarp();

                // ---- step C (exchange): S -> Q via slB ----
                float4 G0 = *(const float4*)(slB + gath);        // u''[8L'..+3]
                float4 G1 = *(const float4*)(slB + gath + 16);   // u''[8L'+4..+7]
                add2(t0, t1, G0.x, G0.y, EA.x, EA.y); q0 = fminf(t0, t1);
                add2(t0, t1, G0.z, G0.w, EA.z, EA.w); q1 = fminf(t0, t1);
                add2(t0, t1, G1.x, G1.y, EB.x, EB.y); q2 = fminf(t0, t1);
                add2(t0, t1, G1.z, G1.w, EB.z, EB.w); q3 = fminf(t0, t1);
            }

            __syncwarp();
            if (lane == 0) {
                st_rel(prod, c + 1);
                if (c + 3 < NCHUNK) {
                    mbar_expect_tx(mb0 + b * 8, CBUF_BYTES);
                    bulk_g2s((unsigned)__cvta_generic_to_shared(cbuf + b * CBUF_BYTES),
                             g_cost + (size_t)(c + 3) * ROWS_CHUNK * N_ST,
                             CBUF_BYTES, mb0 + b * 8);
                }
            }
        }
    } else {
        // warp 1: flush 6KB halves (12 rows/chunk) to g_u3
        if (lane == 0) {
            for (int c = 0; c < NCHUNK; ++c) {
                while (ld_acq(prod) < c + 1) { }
                asm volatile("fence.proxy.async.shared::cta;" ::: "memory");
                unsigned ssrc = (unsigned)__cvta_generic_to_shared(ubuf + (c & 1) * UHALF);
                float* gdst = g_u3 + (size_t)c * 12 * 128;
                asm volatile("cp.async.bulk.global.shared::cta.bulk_group [%0], [%1], %2;"
                             :: "l"(gdst), "r"(ssrc), "r"((unsigned)UHALF) : "memory");
                asm volatile("cp.async.bulk.commit_group;" ::: "memory");
                asm volatile("cp.async.bulk.wait_group 0;" ::: "memory");
                st_rel(done, c);
            }
        }
    }
}

// ---------------------------------------------------------------------------
// Phase C: parallel bits. One warp per t; u_t obtained by:
//  t%3==2: direct read of export row (t-2)/3.
//  t%3==0 (t>=3): 1-step local recompute from u_{t-1} (row t/3-1), cost row
//                 t-1 (identity). t==0: bit = 0 constant.
//  t%3==1 (t>=4): 2-step local recompute from u_{t-2} (row (t-1)/3-1),
//                 cost rows t-2, t-1 (both identity). t==1: from u_0 = zeros.
// All recomputes use rnd(a+b)/fminf identical to the reference recursion.
// Then bit = argmin(u_t) % 2, first-index ties (u >= +0 -> uint order).
// ---------------------------------------------------------------------------
__global__ void __launch_bounds__(256) va_bits_kernel(float* __restrict__ out) {
    const int lane = threadIdx.x & 31;
    const int t    = blockIdx.x * 8 + (threadIdx.x >> 5);
    if (t == 0) { if (lane == 0) out[0] = 0.0f; return; }

    float4 uu;
    const int r = t % 3;
    if (r == 2) {
        uu = *(const float4*)(g_u3 + (size_t)((t - 2) / 3) * 128 + lane * 4);
    } else if (r == 0) {
        const float* up = g_u3 + (size_t)(t / 3 - 1) * 128;        // u_{t-1}
        const float* cp = g_cost + (size_t)(t - 1) * N_ST;
        const int ub = (8 * lane) & 127;
        float4 U0 = *(const float4*)(up + ub);
        float4 U1 = *(const float4*)(up + ub + 4);
        float4 C0 = *(const float4*)(cp + 8 * lane);
        float4 C1 = *(const float4*)(cp + 8 * lane + 4);
        uu.x = fminf(U0.x + C0.x, U0.y + C0.y);
        uu.y = fminf(U0.z + C0.z, U0.w + C0.w);
        uu.z = fminf(U1.x + C1.x, U1.y + C1.y);
        uu.w = fminf(U1.z + C1.z, U1.w + C1.w);
    } else if (t == 1) {
        const float* cp = g_cost;                                   // row 0
        float4 C0 = *(const float4*)(cp + 8 * lane);
        float4 C1 = *(const float4*)(cp + 8 * lane + 4);
        uu.x = fminf(C0.x, C0.y);    // u_0 = 0; rnd(0+c) = c exactly
        uu.y = fminf(C0.z, C0.w);
        uu.z = fminf(C1.x, C1.y);
        uu.w = fminf(C1.z, C1.w);
    } else {
        const int G = (t - 1) / 3;                                  // t = 3G+1, G>=1
        const float* up = g_u3 + (size_t)(G - 1) * 128;             // u_{t-2}
        const float* c1 = g_cost + (size_t)(t - 2) * N_ST;
        const float* c2 = g_cost + (size_t)(t - 1) * N_ST;
        const int ub  = (16 * lane) & 127;
        const int cb1 = (16 * lane) & 255;
        float4 V0 = *(const float4*)(up + ub);
        float4 V1 = *(const float4*)(up + ub + 4);
        float4 V2 = *(const float4*)(up + ub + 8);
        float4 V3 = *(const float4*)(up + ub + 12);
        float4 A0 = *(const float4*)(c1 + cb1);
        float4 A1 = *(const float4*)(c1 + cb1 + 4);
        float4 A2 = *(const float4*)(c1 + cb1 + 8);
        float4 A3 = *(const float4*)(c1 + cb1 + 12);
        float w0 = fminf(V0.x + A0.x, V0.y + A0.y);
        float w1 = fminf(V0.z + A0.z, V0.w + A0.w);
        float w2 = fminf(V1.x + A1.x, V1.y + A1.y);
        float w3 = fminf(V1.z + A1.z, V1.w + A1.w);
        float w4 = fminf(V2.x + A2.x, V2.y + A2.y);
        float w5 = fminf(V2.z + A2.z, V2.w + A2.w);
        float w6 = fminf(V3.x + A3.x, V3.y + A3.y);
        float w7 = fminf(V3.z + A3.z, V3.w + A3.w);
        float4 B0 = *(const float4*)(c2 + 8 * lane);
        float4 B1 = *(const float4*)(c2 + 8 * lane + 4);
        uu.x = fminf(w0 + B0.x, w1 + B0.y);
        uu.y = fminf(w2 + B0.z, w3 + B0.w);
        uu.z = fminf(w4 + B1.x, w5 + B1.y);
        uu.w = fminf(w6 + B1.z, w7 + B1.w);
    }

    const int base_li = 4 * lane;
    float lv = uu.x; int li = base_li;
    if (uu.y < lv) { lv = uu.y; li = base_li + 1; }
    if (uu.z < lv) { lv = uu.z; li = base_li + 2; }
    if (uu.w < lv) { lv = uu.w; li = base_li + 3; }
    unsigned lb = __float_as_uint(lv);
    unsigned mv, idx;
    asm volatile("redux.sync.min.u32 %0, %1, 0xffffffff;" : "=r"(mv) : "r"(lb));
    unsigned cand = (lb == mv) ? (unsigned)li : 0xffffffffu;
    asm volatile("redux.sync.min.u32 %0, %1, 0xffffffff;" : "=r"(idx) : "r"(cand));
    if (lane == 0) out[t] = (idx & 1u) ? 1.0f : 0.0f;
}

// ---------------------------------------------------------------------------
// out layout = [detected(T) | confident_bits(T) | confidence(T)], f32.
// ---------------------------------------------------------------------------
extern "C" void kernel_launch(void* const* d_in, const int* in_sizes, int n_in,
                              void* d_out, int out_size) {
    const float* rx = (const float*)d_in[0];
    const float* h  = (const float*)d_in[1];
    if (n_in >= 2 && in_sizes[0] == 8) {   // defensive: inputs swapped
        rx = (const float*)d_in[1];
        h  = (const float*)d_in[0];
    }
    float* out = (float*)d_out;
    cudaFuncSetAttribute(va_viterbi_kernel,
                         cudaFuncAttributeMaxDynamicSharedMemorySize, SMEM_TOTAL);
    va_cost_kernel<<<T_LEN / 8, 256>>>(rx, h, out);
    va_viterbi_kernel<<<1, 64, SMEM_TOTAL>>>();
    va_bits_kernel<<<T_LEN / 8, 256>>>(out);
}

// round 16
// speedup vs baseline: 3.2255x; 1.0665x over previous
#include <cuda_runtime.h>
#include <cuda_bf16.h>
#include <cstdint>

#define T_LEN      131072
#define T_PAD      131076                // divisible by 36
#define N_ST       256
#define ROWS_CHUNK 36
#define CBUF_BYTES (ROWS_CHUNK * 1024)   // 36KB
#define NCHUNK     (T_PAD / ROWS_CHUNK)  // 3641
#define UHALF      6144                  // 12 u slots x 512B per chunk half
#define SMEM_TOTAL (3 * CBUF_BYTES + 2 * UHALF + 128)
#define FLT_MIN_N  1.17549435e-38f

// cost rows t (t>=T_LEN stay zero: device globals zero-init)
static __device__ float g_cost[(size_t)(T_PAD + 64) * N_ST];
// exported u rows: row g = u_{3g+2}, g = 0..NCHUNK*12-1
static __device__ float g_u3[(size_t)(NCHUNK * 12) * 128];

// packed add: (ox,oy) = (a0+b0, a1+b1), each half rn-rounded == scalar FADD
__device__ __forceinline__ void add2(float& ox, float& oy,
                                     float a0, float a1, float b0, float b1) {
    asm("{\n\t.reg .b64 ra, rb, rc;\n\t"
        "mov.b64 ra, {%2, %3};\n\t"
        "mov.b64 rb, {%4, %5};\n\t"
        "add.rn.f32x2 rc, ra, rb;\n\t"
        "mov.b64 {%0, %1}, rc;\n\t}"
        : "=f"(ox), "=f"(oy) : "f"(a0), "f"(a1), "f"(b0), "f"(b1));
}

// ---------------------------------------------------------------------------
// Phase A: parallel likelihoods (R6-validated FTZ emulation). Rows t%3==1
// stored permuted for trellis step B:
//   pos(j) = 128*(j>>7) + 4*((j&63)>>1) + 2*((j>>6)&1) + (j&1)
// ---------------------------------------------------------------------------
__global__ void __launch_bounds__(256) va_cost_kernel(const float* __restrict__ rx,
                                                      const float* __restrict__ h,
                                                      float* __restrict__ out) {
    __shared__ float sp[N_ST];
    __shared__ float hs[8];
    const int tid = threadIdx.x;
    if (tid < 8) hs[tid] = h[tid];
    __syncthreads();
    {
        float acc = 0.0f;
#pragma unroll
        for (int j = 0; j < 8; ++j) {
            float sym = ((tid >> (7 - j)) & 1) ? -1.0f : 1.0f;
            acc += sym * hs[j];
        }
        sp[tid] = acc;
    }
    __syncthreads();

    const int lane = tid & 31;
    const int t    = blockIdx.x * 8 + (tid >> 5);
    const float r  = rx[t];
    const bool permB = (t % 3) == 1;

    float p[8];
    float acc = 0.0f;
#pragma unroll
    for (int k = 0; k < 8; ++k) {
        float d = r - sp[lane + 32 * k];
        float a = (-(d * d)) / 0.2f;
        float e = expf(a);
        p[k] = (e < FLT_MIN_N) ? 0.0f : e;   // FTZ
        acc += p[k];
    }
#pragma unroll
    for (int off = 16; off > 0; off >>= 1)
        acc += __shfl_down_sync(0xffffffffu, acc, off);
    const float S = __shfl_sync(0xffffffffu, acc, 0);

    float bv = -1.0f; int bi = 0;
#pragma unroll
    for (int k = 0; k < 8; ++k) {
        float q = __fdiv_rn(p[k], S);
        q = (q < FLT_MIN_N) ? 0.0f : q;      // FTZ
        int s = lane + 32 * k;
        if (q > bv) { bv = q; bi = s; }
        int pos = s;
        if (permB) {
            int rr = s & 63;
            pos = 128 * (s >> 7) + 4 * (rr >> 1) + 2 * ((s >> 6) & 1) + (rr & 1);
        }
        g_cost[(size_t)t * N_ST + pos] = -logf(q);
    }
#pragma unroll
    for (int off = 16; off > 0; off >>= 1) {
        float ov = __shfl_xor_sync(0xffffffffu, bv, off);
        int   oi = __shfl_xor_sync(0xffffffffu, bi, off);
        if (ov > bv || (ov == bv && oi < bi)) { bv = ov; bi = oi; }
    }

    if (lane == 0) {
        out[T_LEN + t]     = (float)(bi & 1);
        out[2 * T_LEN + t] = bv;
    }
}

// --- asm helpers ------------------------------------------------------------
__device__ __forceinline__ void st_rel(int* p, int v) {
    asm volatile("st.release.cta.shared.b32 [%0], %1;"
                 :: "r"((unsigned)__cvta_generic_to_shared(p)), "r"(v) : "memory");
}
__device__ __forceinline__ int ld_acq(int* p) {
    int v;
    asm volatile("ld.acquire.cta.shared.b32 %0, [%1];"
                 : "=r"(v) : "r"((unsigned)__cvta_generic_to_shared(p)) : "memory");
    return v;
}
__device__ __forceinline__ void mbar_init(unsigned a, unsigned cnt) {
    asm volatile("mbarrier.init.shared.b64 [%0], %1;" :: "r"(a), "r"(cnt) : "memory");
}
__device__ __forceinline__ void mbar_expect_tx(unsigned a, unsigned bytes) {
    asm volatile("mbarrier.arrive.expect_tx.shared.b64 _, [%0], %1;"
                 :: "r"(a), "r"(bytes) : "memory");
}
__device__ __forceinline__ void mbar_wait(unsigned a, int par) {
    asm volatile(
        "{\n\t.reg .pred P;\n"
        "W%=:\n\t"
        "mbarrier.try_wait.parity.acquire.cta.shared::cta.b64 P, [%0], %1, 0x989680;\n\t"
        "@!P bra W%=;\n\t}"
        :: "r"(a), "r"(par) : "memory");
}
__device__ __forceinline__ void bulk_g2s(unsigned sdst, const void* gsrc,
                                         unsigned bytes, unsigned mbar) {
    asm volatile("cp.async.bulk.shared::cta.global.mbarrier::complete_tx::bytes "
                 "[%0], [%1], %2, [%3];"
                 :: "r"(sdst), "l"(gsrc), "r"(bytes), "r"(mbar) : "memory");
}
// ordered smem export/gather (converged-warp handoff; LSU is in-order per warp)
__device__ __forceinline__ void sts_f32(unsigned a, float v) {
    asm volatile("st.shared.f32 [%0], %1;" :: "r"(a), "f"(v) : "memory");
}
__device__ __forceinline__ float4 lds_v4(unsigned a) {
    float4 r;
    asm volatile("ld.shared.v4.f32 {%0,%1,%2,%3}, [%4];"
                 : "=f"(r.x), "=f"(r.y), "=f"(r.z), "=f"(r.w) : "r"(a) : "memory");
    return r;
}

// ---------------------------------------------------------------------------
// Phase B: 3-phase trellis, NO intra-group __syncwarp. The B->C exchange is a
// same-warp smem handoff: the warp is converged for the whole group loop and
// per-warp shared-memory ops retire in program order, so the asm-volatile
// STS (export) followed by asm-volatile LDS (gather) is hazard-free; the
// volatile/memory clobbers pin the compiler order. Exports only u_{3g+2}.
// ---------------------------------------------------------------------------
__global__ void __launch_bounds__(64) va_viterbi_kernel() {
    extern __shared__ char smem[];
    char* cbuf = smem;                       // 3 x 36KB cost buffers
    char* ubuf = smem + 3 * CBUF_BYTES;      // 2 x 6KB u halves (12 slots each)
    char* ctrl = ubuf + 2 * UHALF;
    int*  prod = (int*)(ctrl + 64);
    int*  done = (int*)(ctrl + 96);
    const unsigned mb0 = (unsigned)__cvta_generic_to_shared(ctrl);
    const unsigned ubase = (unsigned)__cvta_generic_to_shared(ubuf);

    const int tid  = threadIdx.x;
    const int lane = tid & 31;
    const int warp = tid >> 5;

    if (tid == 0) {
        mbar_init(mb0, 1); mbar_init(mb0 + 8, 1); mbar_init(mb0 + 16, 1);
        *prod = 0; *done = -1;
    }
    __syncthreads();

    if (warp == 0) {
        if (lane == 0) {
#pragma unroll
            for (int b = 0; b < 3; ++b) {
                mbar_expect_tx(mb0 + b * 8, CBUF_BYTES);
                bulk_g2s((unsigned)__cvta_generic_to_shared(cbuf + b * CBUF_BYTES),
                         g_cost + (size_t)b * ROWS_CHUNK * N_ST, CBUF_BYTES, mb0 + b * 8);
            }
        }

        float q0 = 0.f, q1 = 0.f, q2 = 0.f, q3 = 0.f;   // u_0 in Q layout
        const unsigned off16 = (unsigned)(16 * lane);
        const unsigned off4  = (unsigned)(4 * lane);
        const unsigned gath  = (unsigned)((32 * lane) & 511);
        const unsigned off32 = (unsigned)(32 * lane);

        for (int c = 0; c < NCHUNK; ++c) {
            const int b   = c % 3;
            const int par = (c / 3) & 1;
            mbar_wait(mb0 + b * 8, par);          // cost chunk resident
            while (ld_acq(done) < c - 2) { }      // our u half free

            const char* crow0 = cbuf + b * CBUF_BYTES;
            const unsigned uh = ubase + (unsigned)((c & 1) * UHALF);
#pragma unroll
            for (int g = 0; g < 12; ++g) {
                const char* crow = crow0 + g * 3072;
                float4 CA = *(const float4*)(crow + off16);
                float4 CB = *(const float4*)(crow + 512 + off16);
                float4 DA = *(const float4*)(crow + 1024 + off16);
                float4 DB = *(const float4*)(crow + 1536 + off16);
                float4 EA = *(const float4*)(crow + 2048 + off32);
                float4 EB = *(const float4*)(crow + 2048 + off32 + 16);

                // ---- step A (local): Q -> P ----
                float t0, t1, p0, p1, p2, p3;
                add2(t0, t1, q0, q1, CA.x, CA.y); p0 = fminf(t0, t1);   // u'[2L]
                add2(t0, t1, q2, q3, CA.z, CA.w); p1 = fminf(t0, t1);   // u'[2L+1]
                add2(t0, t1, q0, q1, CB.x, CB.y); p2 = fminf(t0, t1);   // u'[2L+64]
                add2(t0, t1, q2, q3, CB.z, CB.w); p3 = fminf(t0, t1);   // u'[2L+65]

                // ---- step B (local): P -> S, permuted costs; export u_{3g+2} ----
                float s0, s1, s2, s3;
                add2(t0, t1, p0, p1, DA.x, DA.y); s0 = fminf(t0, t1);   // u''[L]
                add2(t0, t1, p2, p3, DA.z, DA.w); s1 = fminf(t0, t1);   // u''[L+32]
                add2(t0, t1, p0, p1, DB.x, DB.y); s2 = fminf(t0, t1);   // u''[L+64]
                add2(t0, t1, p2, p3, DB.z, DB.w); s3 = fminf(t0, t1);   // u''[L+96]
                const unsigned slB = uh + (unsigned)(g * 512);
                sts_f32(slB + off4,        s0);
                sts_f32(slB + 128 + off4,  s1);
                sts_f32(slB + 256 + off4,  s2);
                sts_f32(slB + 384 + off4,  s3);

                // ---- step C (exchange): same-warp ordered gather from slB ----
                float4 G0 = lds_v4(slB + gath);        // u''[8L'..+3]
                float4 G1 = lds_v4(slB + gath + 16);   // u''[8L'+4..+7]
                add2(t0, t1, G0.x, G0.y, EA.x, EA.y); q0 = fminf(t0, t1);
                add2(t0, t1, G0.z, G0.w, EA.z, EA.w); q1 = fminf(t0, t1);
                add2(t0, t1, G1.x, G1.y, EB.x, EB.y); q2 = fminf(t0, t1);
                add2(t0, t1, G1.z, G1.w, EB.z, EB.w); q3 = fminf(t0, t1);
            }

            __syncwarp();   // cross-warp visibility for the flush (1 per 36 steps)
            if (lane == 0) {
                st_rel(prod, c + 1);
                if (c + 3 < NCHUNK) {
                    mbar_expect_tx(mb0 + b * 8, CBUF_BYTES);
                    bulk_g2s((unsigned)__cvta_generic_to_shared(cbuf + b * CBUF_BYTES),
                             g_cost + (size_t)(c + 3) * ROWS_CHUNK * N_ST,
                             CBUF_BYTES, mb0 + b * 8);
                }
            }
        }
    } else {
        // warp 1: flush 6KB halves (12 rows/chunk) to g_u3
        if (lane == 0) {
            for (int c = 0; c < NCHUNK; ++c) {
                while (ld_acq(prod) < c + 1) { }
                asm volatile("fence.proxy.async.shared::cta;" ::: "memory");
                unsigned ssrc = (unsigned)__cvta_generic_to_shared(ubuf + (c & 1) * UHALF);
                float* gdst = g_u3 + (size_t)c * 12 * 128;
                asm volatile("cp.async.bulk.global.shared::cta.bulk_group [%0], [%1], %2;"
                             :: "l"(gdst), "r"(ssrc), "r"((unsigned)UHALF) : "memory");
                asm volatile("cp.async.bulk.commit_group;" ::: "memory");
                asm volatile("cp.async.bulk.wait_group 0;" ::: "memory");
                st_rel(done, c);
            }
        }
    }
}

// ---------------------------------------------------------------------------
// Phase C: parallel bits. One warp per t; u_t obtained by:
//  t%3==2: direct read of export row (t-2)/3.
//  t%3==0 (t>=3): 1-step recompute from u_{t-1}; t==0: bit = 0.
//  t%3==1 (t>=4): 2-step recompute from u_{t-2}; t==1: from u_0 = zeros.
// All recomputes use rnd(a+b)/fminf identical to the reference recursion.
// ---------------------------------------------------------------------------
__global__ void __launch_bounds__(256) va_bits_kernel(float* __restrict__ out) {
    const int lane = threadIdx.x & 31;
    const int t    = blockIdx.x * 8 + (threadIdx.x >> 5);
    if (t == 0) { if (lane == 0) out[0] = 0.0f; return; }

    float4 uu;
    const int r = t % 3;
    if (r == 2) {
        uu = *(const float4*)(g_u3 + (size_t)((t - 2) / 3) * 128 + lane * 4);
    } else if (r == 0) {
        const float* up = g_u3 + (size_t)(t / 3 - 1) * 128;        // u_{t-1}
        const float* cp = g_cost + (size_t)(t - 1) * N_ST;
        const int ub = (8 * lane) & 127;
        float4 U0 = *(const float4*)(up + ub);
        float4 U1 = *(const float4*)(up + ub + 4);
        float4 C0 = *(const float4*)(cp + 8 * lane);
        float4 C1 = *(const float4*)(cp + 8 * lane + 4);
        uu.x = fminf(U0.x + C0.x, U0.y + C0.y);
        uu.y = fminf(U0.z + C0.z, U0.w + C0.w);
        uu.z = fminf(U1.x + C1.x, U1.y + C1.y);
        uu.w = fminf(U1.z + C1.z, U1.w + C1.w);
    } else if (t == 1) {
        const float* cp = g_cost;                                   // row 0
        float4 C0 = *(const float4*)(cp + 8 * lane);
        float4 C1 = *(const float4*)(cp + 8 * lane + 4);
        uu.x = fminf(C0.x, C0.y);    // u_0 = 0; rnd(0+c) = c exactly
        uu.y = fminf(C0.z, C0.w);
        uu.z = fminf(C1.x, C1.y);
        uu.w = fminf(C1.z, C1.w);
    } else {
        const int G = (t - 1) / 3;                                  // t = 3G+1, G>=1
        const float* up = g_u3 + (size_t)(G - 1) * 128;             // u_{t-2}
        const float* c1 = g_cost + (size_t)(t - 2) * N_ST;
        const float* c2 = g_cost + (size_t)(t - 1) * N_ST;
        const int ub  = (16 * lane) & 127;
        const int cb1 = (16 * lane) & 255;
        float4 V0 = *(const float4*)(up + ub);
        float4 V1 = *(const float4*)(up + ub + 4);
        float4 V2 = *(const float4*)(up + ub + 8);
        float4 V3 = *(const float4*)(up + ub + 12);
        float4 A0 = *(const float4*)(c1 + cb1);
        float4 A1 = *(const float4*)(c1 + cb1 + 4);
        float4 A2 = *(const float4*)(c1 + cb1 + 8);
        float4 A3 = *(const float4*)(c1 + cb1 + 12);
        float w0 = fminf(V0.x + A0.x, V0.y + A0.y);
        float w1 = fminf(V0.z + A0.z, V0.w + A0.w);
        float w2 = fminf(V1.x + A1.x, V1.y + A1.y);
        float w3 = fminf(V1.z + A1.z, V1.w + A1.w);
        float w4 = fminf(V2.x + A2.x, V2.y + A2.y);
        float w5 = fminf(V2.z + A2.z, V2.w + A2.w);
        float w6 = fminf(V3.x + A3.x, V3.y + A3.y);
        float w7 = fminf(V3.z + A3.z, V3.w + A3.w);
        float4 B0 = *(const float4*)(c2 + 8 * lane);
        float4 B1 = *(const float4*)(c2 + 8 * lane + 4);
        uu.x = fminf(w0 + B0.x, w1 + B0.y);
        uu.y = fminf(w2 + B0.z, w3 + B0.w);
        uu.z = fminf(w4 + B1.x, w5 + B1.y);
        uu.w = fminf(w6 + B1.z, w7 + B1.w);
    }

    const int base_li = 4 * lane;
    float lv = uu.x; int li = base_li;
    if (uu.y < lv) { lv = uu.y; li = base_li + 1; }
    if (uu.z < lv) { lv = uu.z; li = base_li + 2; }
    if (uu.w < lv) { lv = uu.w; li = base_li + 3; }
    unsigned lb = __float_as_uint(lv);
    unsigned mv, idx;
    asm volatile("redux.sync.min.u32 %0, %1, 0xffffffff;" : "=r"(mv) : "r"(lb));
    unsigned cand = (lb == mv) ? (unsigned)li : 0xffffffffu;
    asm volatile("redux.sync.min.u32 %0, %1, 0xffffffff;" : "=r"(idx) : "r"(cand));
    if (lane == 0) out[t] = (idx & 1u) ? 1.0f : 0.0f;
}

// ---------------------------------------------------------------------------
// out layout = [detected(T) | confident_bits(T) | confidence(T)], f32.
// ---------------------------------------------------------------------------
extern "C" void kernel_launch(void* const* d_in, const int* in_sizes, int n_in,
                              void* d_out, int out_size) {
    const float* rx = (const float*)d_in[0];
    const float* h  = (const float*)d_in[1];
    if (n_in >= 2 && in_sizes[0] == 8) {   // defensive: inputs swapped
        rx = (const float*)d_in[1];
        h  = (const float*)d_in[0];
    }
    float* out = (float*)d_out;
    cudaFuncSetAttribute(va_viterbi_kernel,
                         cudaFuncAttributeMaxDynamicSharedMemorySize, SMEM_TOTAL);
    va_cost_kernel<<<T_LEN / 8, 256>>>(rx, h, out);
    va_viterbi_kernel<<<1, 64, SMEM_TOTAL>>>();
    va_bits_kernel<<<T_LEN / 8, 256>>>(out);
}